// round 16
// baseline (speedup 1.0000x reference)
#include <cuda_runtime.h>
#include <cstdint>

#define NPTS 524288
#define TPB  128
#define NCTA 592              // 148 SMs x 4 CTAs
#define EMB  32
#define DIRD 27
#define FEAT 15
#define LAT  128
#define RGBK (EMB + DIRD + FEAT)   // 74

// transposed scratch [k][pt]
__device__ float g_a[64ULL * NPTS];    // occ L0 outputs
__device__ float g_x[74ULL * NPTS];    // dir 0..26 | feat 27..41 | e 42..73
__device__ float g_r[64ULL * NPTS];    // rgb L0 outputs

typedef unsigned long long u64t;

#define FMA_F32X2(d, a, b, c) \
    asm("fma.rn.f32x2 %0, %1, %2, %3;" : "=l"(d) : "l"(a), "l"(b), "l"(c))
#define PACK_SPLAT(out, x) \
    asm("mov.b64 %0, {%1, %1};" : "=l"(out) : "r"(__float_as_uint(x)))
#define UNPACK_F32X2U(lo, hi, in) \
    asm("mov.b64 {%0, %1}, %2;" : "=r"(lo), "=r"(hi) : "l"(in))

__device__ __forceinline__ float sp_fast(float x) {
    float e = __expf(x);
    float y = __logf(1.0f + e);
    return (x > 20.0f) ? x : y;
}
__device__ __forceinline__ float sigmoid_fast(float x) {
    return 1.0f / (1.0f + __expf(-x));
}

// ---- 2-point quarter step (16 neurons) ----
#define QSTEP(Q0, Q1, xs0, xs1, wptr) do { \
    const ulonglong2* _wr = (const ulonglong2*)(wptr); \
    ulonglong2 _wa = _wr[0], _wb = _wr[1], _wc = _wr[2], _wd = _wr[3]; \
    FMA_F32X2(Q0[0], xs0, _wa.x, Q0[0]); \
    FMA_F32X2(Q0[1], xs0, _wa.y, Q0[1]); \
    FMA_F32X2(Q0[2], xs0, _wb.x, Q0[2]); \
    FMA_F32X2(Q0[3], xs0, _wb.y, Q0[3]); \
    FMA_F32X2(Q0[4], xs0, _wc.x, Q0[4]); \
    FMA_F32X2(Q0[5], xs0, _wc.y, Q0[5]); \
    FMA_F32X2(Q0[6], xs0, _wd.x, Q0[6]); \
    FMA_F32X2(Q0[7], xs0, _wd.y, Q0[7]); \
    FMA_F32X2(Q1[0], xs1, _wa.x, Q1[0]); \
    FMA_F32X2(Q1[1], xs1, _wa.y, Q1[1]); \
    FMA_F32X2(Q1[2], xs1, _wb.x, Q1[2]); \
    FMA_F32X2(Q1[3], xs1, _wb.y, Q1[3]); \
    FMA_F32X2(Q1[4], xs1, _wc.x, Q1[4]); \
    FMA_F32X2(Q1[5], xs1, _wc.y, Q1[5]); \
    FMA_F32X2(Q1[6], xs1, _wd.x, Q1[6]); \
    FMA_F32X2(Q1[7], xs1, _wd.y, Q1[7]); \
} while (0)

// ---- 4-point quarter step (16 neurons) ----
#define K4STEP(Q, xs0, xs1, xs2, xs3, wptr) do { \
    const ulonglong2* _wr = (const ulonglong2*)(wptr); \
    ulonglong2 _wa = _wr[0], _wb = _wr[1], _wc = _wr[2], _wd = _wr[3]; \
    FMA_F32X2(Q[0][0], xs0, _wa.x, Q[0][0]); \
    FMA_F32X2(Q[0][1], xs0, _wa.y, Q[0][1]); \
    FMA_F32X2(Q[0][2], xs0, _wb.x, Q[0][2]); \
    FMA_F32X2(Q[0][3], xs0, _wb.y, Q[0][3]); \
    FMA_F32X2(Q[0][4], xs0, _wc.x, Q[0][4]); \
    FMA_F32X2(Q[0][5], xs0, _wc.y, Q[0][5]); \
    FMA_F32X2(Q[0][6], xs0, _wd.x, Q[0][6]); \
    FMA_F32X2(Q[0][7], xs0, _wd.y, Q[0][7]); \
    FMA_F32X2(Q[1][0], xs1, _wa.x, Q[1][0]); \
    FMA_F32X2(Q[1][1], xs1, _wa.y, Q[1][1]); \
    FMA_F32X2(Q[1][2], xs1, _wb.x, Q[1][2]); \
    FMA_F32X2(Q[1][3], xs1, _wb.y, Q[1][3]); \
    FMA_F32X2(Q[1][4], xs1, _wc.x, Q[1][4]); \
    FMA_F32X2(Q[1][5], xs1, _wc.y, Q[1][5]); \
    FMA_F32X2(Q[1][6], xs1, _wd.x, Q[1][6]); \
    FMA_F32X2(Q[1][7], xs1, _wd.y, Q[1][7]); \
    FMA_F32X2(Q[2][0], xs2, _wa.x, Q[2][0]); \
    FMA_F32X2(Q[2][1], xs2, _wa.y, Q[2][1]); \
    FMA_F32X2(Q[2][2], xs2, _wb.x, Q[2][2]); \
    FMA_F32X2(Q[2][3], xs2, _wb.y, Q[2][3]); \
    FMA_F32X2(Q[2][4], xs2, _wc.x, Q[2][4]); \
    FMA_F32X2(Q[2][5], xs2, _wc.y, Q[2][5]); \
    FMA_F32X2(Q[2][6], xs2, _wd.x, Q[2][6]); \
    FMA_F32X2(Q[2][7], xs2, _wd.y, Q[2][7]); \
    FMA_F32X2(Q[3][0], xs3, _wa.x, Q[3][0]); \
    FMA_F32X2(Q[3][1], xs3, _wa.y, Q[3][1]); \
    FMA_F32X2(Q[3][2], xs3, _wb.x, Q[3][2]); \
    FMA_F32X2(Q[3][3], xs3, _wb.y, Q[3][3]); \
    FMA_F32X2(Q[3][4], xs3, _wc.x, Q[3][4]); \
    FMA_F32X2(Q[3][5], xs3, _wc.y, Q[3][5]); \
    FMA_F32X2(Q[3][6], xs3, _wd.x, Q[3][6]); \
    FMA_F32X2(Q[3][7], xs3, _wd.y, Q[3][7]); \
} while (0)

// ======================= k1a: occ layer 0 (2-pt, persistent) ===============
__global__ __launch_bounds__(TPB, 4)
void k1a_occ0(const float* __restrict__ embedded,
              const float* __restrict__ occ_W0,
              const float* __restrict__ occ_b0)
{
    __shared__ float sw[32*64 + 64];
    const int tid = threadIdx.x;
    for (int t = tid; t < 32*64; t += TPB) sw[t] = occ_W0[t];
    if (tid < 64) sw[32*64 + tid] = occ_b0[tid];
    __syncthreads();

    const int nCh = NPTS / (2 * TPB);   // 2048
    for (int ch = blockIdx.x; ch < nCh; ch += NCTA) {
        const int p0 = ch * (2*TPB) + 2*tid;

        float e0[EMB], e1[EMB];
        {
            const float4* q0 = (const float4*)(embedded + (size_t)p0 * EMB);
            #pragma unroll
            for (int q = 0; q < EMB/4; q++) {
                float4 v0 = q0[q], v1 = q0[q + EMB/4];
                e0[4*q]=v0.x; e0[4*q+1]=v0.y; e0[4*q+2]=v0.z; e0[4*q+3]=v0.w;
                e1[4*q]=v1.x; e1[4*q+1]=v1.y; e1[4*q+2]=v1.z; e1[4*q+3]=v1.w;
            }
        }

        // transpose e into g_x rows 42..73
        #pragma unroll
        for (int k = 0; k < EMB; k++)
            *(float2*)(g_x + (size_t)(42 + k) * NPTS + p0) = make_float2(e0[k], e1[k]);

        #pragma unroll
        for (int q = 0; q < 4; q++) {
            u64t Q0[8], Q1[8];
            const u64t* bp = (const u64t*)(sw + 32*64) + q*8;
            #pragma unroll
            for (int m = 0; m < 8; m++) { Q0[m] = bp[m]; Q1[m] = bp[m]; }

            #pragma unroll 8
            for (int k = 0; k < EMB; k++) {
                u64t xs0, xs1;
                PACK_SPLAT(xs0, e0[k]);
                PACK_SPLAT(xs1, e1[k]);
                QSTEP(Q0, Q1, xs0, xs1, sw + k*64 + q*16);
            }

            #pragma unroll
            for (int m = 0; m < 8; m++) {
                unsigned l0, h0, l1, h1;
                UNPACK_F32X2U(l0, h0, Q0[m]);
                UNPACK_F32X2U(l1, h1, Q1[m]);
                float2 va = make_float2(sp_fast(__uint_as_float(l0)), sp_fast(__uint_as_float(l1)));
                float2 vb = make_float2(sp_fast(__uint_as_float(h0)), sp_fast(__uint_as_float(h1)));
                *(float2*)(g_a + (size_t)(q*16 + 2*m)     * NPTS + p0) = va;
                *(float2*)(g_a + (size_t)(q*16 + 2*m + 1) * NPTS + p0) = vb;
            }
        }
    }
}

// ========== k1b: occ L1+L2 fused (2-pt, persistent) + dir copy =============
__global__ __launch_bounds__(TPB, 4)
void k1b_occ12(const float* __restrict__ embedded_dir,
               const float* __restrict__ occ_W1, const float* __restrict__ occ_b1,
               const float* __restrict__ occ_W2, const float* __restrict__ occ_b2,
               float* __restrict__ out)
{
    __shared__ float sw[64*64 + 64*16 + 64 + 16];
    const int W2o = 64*64, B1o = W2o + 64*16, B2o = B1o + 64;
    const int tid = threadIdx.x;
    for (int t = tid; t < 64*64; t += TPB) sw[t] = occ_W1[t];
    for (int t = tid; t < 64*16; t += TPB) sw[W2o + t] = occ_W2[t];
    if (tid < 64) sw[B1o + tid] = occ_b1[tid];
    if (tid >= 64 && tid < 80) sw[B2o + tid - 64] = occ_b2[tid - 64];
    __syncthreads();

    const int nCh = NPTS / (2 * TPB);   // 2048
    for (int ch = blockIdx.x; ch < nCh; ch += NCTA) {
        const int p0 = ch * (2*TPB) + 2*tid;

        u64t C0[8], C1[8];
        {
            const u64t* bp = (const u64t*)(sw + B2o);
            #pragma unroll
            for (int m = 0; m < 8; m++) { C0[m] = bp[m]; C1[m] = bp[m]; }
        }

        #pragma unroll
        for (int q = 0; q < 4; q++) {
            u64t Q0[8], Q1[8];
            const u64t* bp = (const u64t*)(sw + B1o) + q*8;
            #pragma unroll
            for (int m = 0; m < 8; m++) { Q0[m] = bp[m]; Q1[m] = bp[m]; }

            #pragma unroll 8
            for (int k = 0; k < 64; k++) {
                float2 xv = *(const float2*)(g_a + (size_t)k * NPTS + p0);
                u64t xs0, xs1;
                PACK_SPLAT(xs0, xv.x);
                PACK_SPLAT(xs1, xv.y);
                QSTEP(Q0, Q1, xs0, xs1, sw + k*64 + q*16);
            }

            float h0[16], h1[16];
            #pragma unroll
            for (int m = 0; m < 8; m++) {
                unsigned lo, hi;
                UNPACK_F32X2U(lo, hi, Q0[m]);
                h0[2*m]   = sp_fast(__uint_as_float(lo));
                h0[2*m+1] = sp_fast(__uint_as_float(hi));
                UNPACK_F32X2U(lo, hi, Q1[m]);
                h1[2*m]   = sp_fast(__uint_as_float(lo));
                h1[2*m+1] = sp_fast(__uint_as_float(hi));
            }

            #pragma unroll
            for (int kk = 0; kk < 16; kk++) {
                const int kq = q*16 + kk;
                u64t xs0, xs1;
                PACK_SPLAT(xs0, h0[kk]);
                PACK_SPLAT(xs1, h1[kk]);
                QSTEP(C0, C1, xs0, xs1, sw + W2o + kq*16);
            }
        }

        float hid0[16], hid1[16];
        #pragma unroll
        for (int m = 0; m < 8; m++) {
            unsigned lo, hi;
            UNPACK_F32X2U(lo, hi, C0[m]);
            hid0[2*m]   = __uint_as_float(lo);
            hid0[2*m+1] = __uint_as_float(hi);
            UNPACK_F32X2U(lo, hi, C1[m]);
            hid1[2*m]   = __uint_as_float(lo);
            hid1[2*m+1] = __uint_as_float(hi);
        }

        const float occ0 = 1.0f - __expf(-sp_fast(hid0[0]));
        const float occ1 = 1.0f - __expf(-sp_fast(hid1[0]));
        out[(size_t)NPTS*4 + p0]     = occ0;
        out[(size_t)NPTS*4 + p0 + 1] = occ1;

        #pragma unroll
        for (int n = 1; n < 16; n++)
            *(float2*)(g_x + (size_t)(DIRD + n - 1) * NPTS + p0) =
                make_float2(hid0[n], hid1[n]);

        {
            const float* d0 = embedded_dir + (size_t)p0 * DIRD;
            const float* d1 = d0 + DIRD;
            #pragma unroll
            for (int k = 0; k < DIRD; k++)
                *(float2*)(g_x + (size_t)k * NPTS + p0) = make_float2(d0[k], d1[k]);
        }
    }
}

// ====== k2: rgb layer 0 (74 -> 64 sp, latent-folded), 4-pt persistent ======
__global__ __launch_bounds__(TPB, 4)
void k2_rgb0(const float* __restrict__ rgb_W0, const float* __restrict__ rgb_b0,
             const float* __restrict__ rgb_latent,
             const int*   __restrict__ latent_index)
{
    __shared__ float sw[74*64 + 64];
    const int LATBo = 74*64;
    const int tid = threadIdx.x;
    for (int t = tid; t < 74*64; t += TPB) {
        int r = t >> 6, j = t & 63;
        int src = (r < 42) ? (r + 32) : (r - 42);
        sw[t] = rgb_W0[src * 64 + j];
    }
    if (tid >= 64) {
        const int j = tid - 64;
        const int li = *latent_index;
        const float* lrow = rgb_latent + li * LAT;
        float acc = rgb_b0[j];
        #pragma unroll 8
        for (int l = 0; l < LAT; l++)
            acc = fmaf(lrow[l], rgb_W0[(RGBK + l) * 64 + j], acc);
        sw[LATBo + j] = acc;
    }
    __syncthreads();

    const int nCh = NPTS / (4 * TPB);   // 1024
    for (int ch = blockIdx.x; ch < nCh; ch += NCTA) {
        const int p0 = (ch * TPB + tid) * 4;

        #pragma unroll
        for (int q = 0; q < 4; q++) {
            u64t Q[4][8];
            {
                const u64t* bp = (const u64t*)(sw + LATBo) + q*8;
                #pragma unroll
                for (int m = 0; m < 8; m++) {
                    u64t b = bp[m];
                    Q[0][m] = b; Q[1][m] = b; Q[2][m] = b; Q[3][m] = b;
                }
            }
            #pragma unroll 8
            for (int k = 0; k < RGBK; k++) {
                float4 xv = *(const float4*)(g_x + (size_t)k * NPTS + p0);
                u64t xs0, xs1, xs2, xs3;
                PACK_SPLAT(xs0, xv.x); PACK_SPLAT(xs1, xv.y);
                PACK_SPLAT(xs2, xv.z); PACK_SPLAT(xs3, xv.w);
                K4STEP(Q, xs0, xs1, xs2, xs3, sw + k*64 + q*16);
            }
            #pragma unroll
            for (int m = 0; m < 8; m++) {
                unsigned l0,h0,l1,h1,l2,h2,l3,h3;
                UNPACK_F32X2U(l0, h0, Q[0][m]);
                UNPACK_F32X2U(l1, h1, Q[1][m]);
                UNPACK_F32X2U(l2, h2, Q[2][m]);
                UNPACK_F32X2U(l3, h3, Q[3][m]);
                float4 va = make_float4(sp_fast(__uint_as_float(l0)), sp_fast(__uint_as_float(l1)),
                                        sp_fast(__uint_as_float(l2)), sp_fast(__uint_as_float(l3)));
                float4 vb = make_float4(sp_fast(__uint_as_float(h0)), sp_fast(__uint_as_float(h1)),
                                        sp_fast(__uint_as_float(h2)), sp_fast(__uint_as_float(h3)));
                *(float4*)(g_r + (size_t)(q*16 + 2*m)     * NPTS + p0) = va;
                *(float4*)(g_r + (size_t)(q*16 + 2*m + 1) * NPTS + p0) = vb;
            }
        }
    }
}

// ====== k3: rgb L1+L2 fused (4-pt, persistent) + output ====================
__global__ __launch_bounds__(TPB, 4)
void k3_rgb12(const float* __restrict__ rgb_W1, const float* __restrict__ rgb_b1,
              const float* __restrict__ rgb_W2, const float* __restrict__ rgb_b2,
              float* __restrict__ out)
{
    __shared__ float sw[64*64 + 64*4 + 64 + 4];
    const int W2o = 64*64, B1o = W2o + 64*4, B2o = B1o + 64;
    const int tid = threadIdx.x;
    for (int t = tid; t < 64*64; t += TPB) sw[t] = rgb_W1[t];
    for (int t = tid; t < 64*3; t += TPB) {
        int k = t / 3, j = t - 3*k;
        sw[W2o + k*4 + j] = rgb_W2[t];
    }
    for (int t = tid; t < 64; t += TPB) sw[W2o + t*4 + 3] = 0.0f;
    if (tid < 64) sw[B1o + tid] = rgb_b1[tid];
    if (tid >= 64 && tid < 67) sw[B2o + tid - 64] = rgb_b2[tid - 64];
    if (tid == 67) sw[B2o + 3] = 0.0f;
    __syncthreads();

    const int nCh = NPTS / (4 * TPB);   // 1024
    for (int ch = blockIdx.x; ch < nCh; ch += NCTA) {
        const int p0 = (ch * TPB + tid) * 4;

        float c[4][3];
        #pragma unroll
        for (int pt = 0; pt < 4; pt++) {
            c[pt][0] = sw[B2o+0]; c[pt][1] = sw[B2o+1]; c[pt][2] = sw[B2o+2];
        }

        #pragma unroll
        for (int q = 0; q < 4; q++) {
            u64t Q[4][8];
            {
                const u64t* bp = (const u64t*)(sw + B1o) + q*8;
                #pragma unroll
                for (int m = 0; m < 8; m++) {
                    u64t b = bp[m];
                    Q[0][m] = b; Q[1][m] = b; Q[2][m] = b; Q[3][m] = b;
                }
            }
            #pragma unroll 8
            for (int k = 0; k < 64; k++) {
                float4 xv = *(const float4*)(g_r + (size_t)k * NPTS + p0);
                u64t xs0, xs1, xs2, xs3;
                PACK_SPLAT(xs0, xv.x); PACK_SPLAT(xs1, xv.y);
                PACK_SPLAT(xs2, xv.z); PACK_SPLAT(xs3, xv.w);
                K4STEP(Q, xs0, xs1, xs2, xs3, sw + k*64 + q*16);
            }

            #pragma unroll
            for (int m = 0; m < 8; m++) {
                unsigned lo, hi;
                float h[4][2];
                UNPACK_F32X2U(lo, hi, Q[0][m]);
                h[0][0] = sp_fast(__uint_as_float(lo)); h[0][1] = sp_fast(__uint_as_float(hi));
                UNPACK_F32X2U(lo, hi, Q[1][m]);
                h[1][0] = sp_fast(__uint_as_float(lo)); h[1][1] = sp_fast(__uint_as_float(hi));
                UNPACK_F32X2U(lo, hi, Q[2][m]);
                h[2][0] = sp_fast(__uint_as_float(lo)); h[2][1] = sp_fast(__uint_as_float(hi));
                UNPACK_F32X2U(lo, hi, Q[3][m]);
                h[3][0] = sp_fast(__uint_as_float(lo)); h[3][1] = sp_fast(__uint_as_float(hi));

                const int kq = q*16 + 2*m;
                float4 wA = *(const float4*)(sw + W2o + kq*4);
                float4 wB = *(const float4*)(sw + W2o + (kq+1)*4);
                #pragma unroll
                for (int pt = 0; pt < 4; pt++) {
                    c[pt][0] = fmaf(h[pt][0], wA.x, c[pt][0]);
                    c[pt][1] = fmaf(h[pt][0], wA.y, c[pt][1]);
                    c[pt][2] = fmaf(h[pt][0], wA.z, c[pt][2]);
                    c[pt][0] = fmaf(h[pt][1], wB.x, c[pt][0]);
                    c[pt][1] = fmaf(h[pt][1], wB.y, c[pt][1]);
                    c[pt][2] = fmaf(h[pt][1], wB.z, c[pt][2]);
                }
            }
        }

        float4 ov = *(const float4*)(out + (size_t)NPTS*4 + p0);
        float occ4[4] = {ov.x, ov.y, ov.z, ov.w};
        float4* o4 = (float4*)out;
        #pragma unroll
        for (int pt = 0; pt < 4; pt++) {
            o4[p0 + pt] = make_float4(sigmoid_fast(c[pt][0]), sigmoid_fast(c[pt][1]),
                                      sigmoid_fast(c[pt][2]), occ4[pt]);
        }
    }
}

extern "C" void kernel_launch(void* const* d_in, const int* in_sizes, int n_in,
                              void* d_out, int out_size) {
    const float* embedded     = (const float*)d_in[0];
    const float* embedded_dir = (const float*)d_in[1];
    const float* occ_W0 = (const float*)d_in[2];
    const float* occ_b0 = (const float*)d_in[3];
    const float* occ_W1 = (const float*)d_in[4];
    const float* occ_b1 = (const float*)d_in[5];
    const float* occ_W2 = (const float*)d_in[6];
    const float* occ_b2 = (const float*)d_in[7];
    const float* rgb_W0 = (const float*)d_in[8];
    const float* rgb_b0 = (const float*)d_in[9];
    const float* rgb_W1 = (const float*)d_in[10];
    const float* rgb_b1 = (const float*)d_in[11];
    const float* rgb_W2 = (const float*)d_in[12];
    const float* rgb_b2 = (const float*)d_in[13];
    const float* rgb_latent = (const float*)d_in[14];
    const int*   latent_index = (const int*)d_in[15];
    float* out = (float*)d_out;

    k1a_occ0 <<<NCTA, TPB>>>(embedded, occ_W0, occ_b0);
    k1b_occ12<<<NCTA, TPB>>>(embedded_dir, occ_W1, occ_b1, occ_W2, occ_b2, out);
    k2_rgb0  <<<NCTA, TPB>>>(rgb_W0, rgb_b0, rgb_latent, latent_index);
    k3_rgb12 <<<NCTA, TPB>>>(rgb_W1, rgb_b1, rgb_W2, rgb_b2, out);
}

// round 17
// speedup vs baseline: 1.3680x; 1.3680x over previous
#include <cuda_runtime.h>
#include <cstdint>

#define NPTS 524288
#define TPB  128
#define EMB  32
#define DIRD 27
#define FEAT 15
#define LAT  128
#define RGBK (EMB + DIRD + FEAT)   // 74

// transposed scratch [k][pt]
__device__ float g_a[64ULL * NPTS];    // occ L0 outputs
__device__ float g_x[74ULL * NPTS];    // dir 0..26 | feat 27..41 | e 42..73
__device__ float g_r[64ULL * NPTS];    // rgb L0 outputs

typedef unsigned long long u64t;

#define FMA_F32X2(d, a, b, c) \
    asm("fma.rn.f32x2 %0, %1, %2, %3;" : "=l"(d) : "l"(a), "l"(b), "l"(c))
#define PACK_SPLAT(out, x) \
    asm("mov.b64 %0, {%1, %1};" : "=l"(out) : "r"(__float_as_uint(x)))
#define UNPACK_F32X2U(lo, hi, in) \
    asm("mov.b64 {%0, %1}, %2;" : "=r"(lo), "=r"(hi) : "l"(in))

__device__ __forceinline__ float sp_fast(float x) {
    float e = __expf(x);
    float y = __logf(1.0f + e);
    return (x > 20.0f) ? x : y;
}
__device__ __forceinline__ float sigmoid_fast(float x) {
    return 1.0f / (1.0f + __expf(-x));
}

// ---- 2-point quarter step (16 neurons): 4 LDS.128 : 16 FFMA2 ----
#define QSTEP(Q0, Q1, xs0, xs1, wptr) do { \
    const ulonglong2* _wr = (const ulonglong2*)(wptr); \
    ulonglong2 _wa = _wr[0], _wb = _wr[1], _wc = _wr[2], _wd = _wr[3]; \
    FMA_F32X2(Q0[0], xs0, _wa.x, Q0[0]); \
    FMA_F32X2(Q0[1], xs0, _wa.y, Q0[1]); \
    FMA_F32X2(Q0[2], xs0, _wb.x, Q0[2]); \
    FMA_F32X2(Q0[3], xs0, _wb.y, Q0[3]); \
    FMA_F32X2(Q0[4], xs0, _wc.x, Q0[4]); \
    FMA_F32X2(Q0[5], xs0, _wc.y, Q0[5]); \
    FMA_F32X2(Q0[6], xs0, _wd.x, Q0[6]); \
    FMA_F32X2(Q0[7], xs0, _wd.y, Q0[7]); \
    FMA_F32X2(Q1[0], xs1, _wa.x, Q1[0]); \
    FMA_F32X2(Q1[1], xs1, _wa.y, Q1[1]); \
    FMA_F32X2(Q1[2], xs1, _wb.x, Q1[2]); \
    FMA_F32X2(Q1[3], xs1, _wb.y, Q1[3]); \
    FMA_F32X2(Q1[4], xs1, _wc.x, Q1[4]); \
    FMA_F32X2(Q1[5], xs1, _wc.y, Q1[5]); \
    FMA_F32X2(Q1[6], xs1, _wd.x, Q1[6]); \
    FMA_F32X2(Q1[7], xs1, _wd.y, Q1[7]); \
} while (0)

// ---- 4-point quarter step (16 neurons): 4 LDS.128 : 32 FFMA2 ----
#define K4STEP(Q, xs0, xs1, xs2, xs3, wptr) do { \
    const ulonglong2* _wr = (const ulonglong2*)(wptr); \
    ulonglong2 _wa = _wr[0], _wb = _wr[1], _wc = _wr[2], _wd = _wr[3]; \
    FMA_F32X2(Q[0][0], xs0, _wa.x, Q[0][0]); \
    FMA_F32X2(Q[0][1], xs0, _wa.y, Q[0][1]); \
    FMA_F32X2(Q[0][2], xs0, _wb.x, Q[0][2]); \
    FMA_F32X2(Q[0][3], xs0, _wb.y, Q[0][3]); \
    FMA_F32X2(Q[0][4], xs0, _wc.x, Q[0][4]); \
    FMA_F32X2(Q[0][5], xs0, _wc.y, Q[0][5]); \
    FMA_F32X2(Q[0][6], xs0, _wd.x, Q[0][6]); \
    FMA_F32X2(Q[0][7], xs0, _wd.y, Q[0][7]); \
    FMA_F32X2(Q[1][0], xs1, _wa.x, Q[1][0]); \
    FMA_F32X2(Q[1][1], xs1, _wa.y, Q[1][1]); \
    FMA_F32X2(Q[1][2], xs1, _wb.x, Q[1][2]); \
    FMA_F32X2(Q[1][3], xs1, _wb.y, Q[1][3]); \
    FMA_F32X2(Q[1][4], xs1, _wc.x, Q[1][4]); \
    FMA_F32X2(Q[1][5], xs1, _wc.y, Q[1][5]); \
    FMA_F32X2(Q[1][6], xs1, _wd.x, Q[1][6]); \
    FMA_F32X2(Q[1][7], xs1, _wd.y, Q[1][7]); \
    FMA_F32X2(Q[2][0], xs2, _wa.x, Q[2][0]); \
    FMA_F32X2(Q[2][1], xs2, _wa.y, Q[2][1]); \
    FMA_F32X2(Q[2][2], xs2, _wb.x, Q[2][2]); \
    FMA_F32X2(Q[2][3], xs2, _wb.y, Q[2][3]); \
    FMA_F32X2(Q[2][4], xs2, _wc.x, Q[2][4]); \
    FMA_F32X2(Q[2][5], xs2, _wc.y, Q[2][5]); \
    FMA_F32X2(Q[2][6], xs2, _wd.x, Q[2][6]); \
    FMA_F32X2(Q[2][7], xs2, _wd.y, Q[2][7]); \
    FMA_F32X2(Q[3][0], xs3, _wa.x, Q[3][0]); \
    FMA_F32X2(Q[3][1], xs3, _wa.y, Q[3][1]); \
    FMA_F32X2(Q[3][2], xs3, _wb.x, Q[3][2]); \
    FMA_F32X2(Q[3][3], xs3, _wb.y, Q[3][3]); \
    FMA_F32X2(Q[3][4], xs3, _wc.x, Q[3][4]); \
    FMA_F32X2(Q[3][5], xs3, _wc.y, Q[3][5]); \
    FMA_F32X2(Q[3][6], xs3, _wd.x, Q[3][6]); \
    FMA_F32X2(Q[3][7], xs3, _wd.y, Q[3][7]); \
} while (0)

// ======================= k1a: occ layer 0 (2-pt) + e transpose =============
__global__ __launch_bounds__(TPB, 4)
void k1a_occ0(const float* __restrict__ embedded,
              const float* __restrict__ occ_W0,
              const float* __restrict__ occ_b0)
{
    __shared__ float sw[32*64 + 64];
    const int tid = threadIdx.x;
    for (int t = tid; t < 32*64; t += TPB) sw[t] = occ_W0[t];
    if (tid < 64) sw[32*64 + tid] = occ_b0[tid];
    __syncthreads();

    const int p0 = blockIdx.x * (2*TPB) + 2*tid;

    float e0[EMB], e1[EMB];
    {
        const float4* q0 = (const float4*)(embedded + (size_t)p0 * EMB);
        #pragma unroll
        for (int q = 0; q < EMB/4; q++) {
            float4 v0 = q0[q], v1 = q0[q + EMB/4];
            e0[4*q]=v0.x; e0[4*q+1]=v0.y; e0[4*q+2]=v0.z; e0[4*q+3]=v0.w;
            e1[4*q]=v1.x; e1[4*q+1]=v1.y; e1[4*q+2]=v1.z; e1[4*q+3]=v1.w;
        }
    }

    // transpose e into g_x rows 42..73
    #pragma unroll
    for (int k = 0; k < EMB; k++)
        *(float2*)(g_x + (size_t)(42 + k) * NPTS + p0) = make_float2(e0[k], e1[k]);

    #pragma unroll
    for (int q = 0; q < 4; q++) {
        u64t Q0[8], Q1[8];
        const u64t* bp = (const u64t*)(sw + 32*64) + q*8;
        #pragma unroll
        for (int m = 0; m < 8; m++) { Q0[m] = bp[m]; Q1[m] = bp[m]; }

        #pragma unroll 8
        for (int k = 0; k < EMB; k++) {
            u64t xs0, xs1;
            PACK_SPLAT(xs0, e0[k]);
            PACK_SPLAT(xs1, e1[k]);
            QSTEP(Q0, Q1, xs0, xs1, sw + k*64 + q*16);
        }

        #pragma unroll
        for (int m = 0; m < 8; m++) {
            unsigned l0, h0, l1, h1;
            UNPACK_F32X2U(l0, h0, Q0[m]);
            UNPACK_F32X2U(l1, h1, Q1[m]);
            float2 va = make_float2(sp_fast(__uint_as_float(l0)), sp_fast(__uint_as_float(l1)));
            float2 vb = make_float2(sp_fast(__uint_as_float(h0)), sp_fast(__uint_as_float(h1)));
            *(float2*)(g_a + (size_t)(q*16 + 2*m)     * NPTS + p0) = va;
            *(float2*)(g_a + (size_t)(q*16 + 2*m + 1) * NPTS + p0) = vb;
        }
    }
}

// ========== k1b: occ L1 (64->64 sp) fused occ L2 (64->16 lin) + dir copy ===
__global__ __launch_bounds__(TPB, 4)
void k1b_occ12(const float* __restrict__ embedded_dir,
               const float* __restrict__ occ_W1, const float* __restrict__ occ_b1,
               const float* __restrict__ occ_W2, const float* __restrict__ occ_b2,
               float* __restrict__ out)
{
    __shared__ float sw[64*64 + 64*16 + 64 + 16];
    const int W2o = 64*64, B1o = W2o + 64*16, B2o = B1o + 64;
    const int tid = threadIdx.x;
    for (int t = tid; t < 64*64; t += TPB) sw[t] = occ_W1[t];
    for (int t = tid; t < 64*16; t += TPB) sw[W2o + t] = occ_W2[t];
    if (tid < 64) sw[B1o + tid] = occ_b1[tid];
    if (tid >= 64 && tid < 80) sw[B2o + tid - 64] = occ_b2[tid - 64];
    __syncthreads();

    const int p0 = blockIdx.x * (2*TPB) + 2*tid;

    u64t C0[8], C1[8];
    {
        const u64t* bp = (const u64t*)(sw + B2o);
        #pragma unroll
        for (int m = 0; m < 8; m++) { C0[m] = bp[m]; C1[m] = bp[m]; }
    }

    #pragma unroll
    for (int q = 0; q < 4; q++) {
        u64t Q0[8], Q1[8];
        const u64t* bp = (const u64t*)(sw + B1o) + q*8;
        #pragma unroll
        for (int m = 0; m < 8; m++) { Q0[m] = bp[m]; Q1[m] = bp[m]; }

        #pragma unroll 8
        for (int k = 0; k < 64; k++) {
            float2 xv = *(const float2*)(g_a + (size_t)k * NPTS + p0);
            u64t xs0, xs1;
            PACK_SPLAT(xs0, xv.x);
            PACK_SPLAT(xs1, xv.y);
            QSTEP(Q0, Q1, xs0, xs1, sw + k*64 + q*16);
        }

        float h0[16], h1[16];
        #pragma unroll
        for (int m = 0; m < 8; m++) {
            unsigned lo, hi;
            UNPACK_F32X2U(lo, hi, Q0[m]);
            h0[2*m]   = sp_fast(__uint_as_float(lo));
            h0[2*m+1] = sp_fast(__uint_as_float(hi));
            UNPACK_F32X2U(lo, hi, Q1[m]);
            h1[2*m]   = sp_fast(__uint_as_float(lo));
            h1[2*m+1] = sp_fast(__uint_as_float(hi));
        }

        #pragma unroll
        for (int kk = 0; kk < 16; kk++) {
            const int kq = q*16 + kk;
            u64t xs0, xs1;
            PACK_SPLAT(xs0, h0[kk]);
            PACK_SPLAT(xs1, h1[kk]);
            QSTEP(C0, C1, xs0, xs1, sw + W2o + kq*16);
        }
    }

    float hid0[16], hid1[16];
    #pragma unroll
    for (int m = 0; m < 8; m++) {
        unsigned lo, hi;
        UNPACK_F32X2U(lo, hi, C0[m]);
        hid0[2*m]   = __uint_as_float(lo);
        hid0[2*m+1] = __uint_as_float(hi);
        UNPACK_F32X2U(lo, hi, C1[m]);
        hid1[2*m]   = __uint_as_float(lo);
        hid1[2*m+1] = __uint_as_float(hi);
    }

    const float occ0 = 1.0f - __expf(-sp_fast(hid0[0]));
    const float occ1 = 1.0f - __expf(-sp_fast(hid1[0]));
    out[(size_t)NPTS*4 + p0]     = occ0;
    out[(size_t)NPTS*4 + p0 + 1] = occ1;

    // feat -> g_x rows 27..41
    #pragma unroll
    for (int n = 1; n < 16; n++)
        *(float2*)(g_x + (size_t)(DIRD + n - 1) * NPTS + p0) =
            make_float2(hid0[n], hid1[n]);

    // dir -> g_x rows 0..26
    {
        const float* d0 = embedded_dir + (size_t)p0 * DIRD;
        const float* d1 = d0 + DIRD;
        #pragma unroll
        for (int k = 0; k < DIRD; k++)
            *(float2*)(g_x + (size_t)k * NPTS + p0) = make_float2(d0[k], d1[k]);
    }
}

// ====== k2: rgb layer 0 (74 -> 64 sp, latent-folded), 4-pt unified stream ==
// sw row r matches g_x row r: r<42 -> rgb_W0 row r+32 ; r>=42 -> rgb_W0 row r-42
__global__ __launch_bounds__(TPB, 4)
void k2_rgb0(const float* __restrict__ rgb_W0, const float* __restrict__ rgb_b0,
             const float* __restrict__ rgb_latent,
             const int*   __restrict__ latent_index)
{
    __shared__ float sw[74*64 + 64];
    const int LATBo = 74*64;
    const int tid = threadIdx.x;
    for (int t = tid; t < 74*64; t += TPB) {
        int r = t >> 6, j = t & 63;
        int src = (r < 42) ? (r + 32) : (r - 42);
        sw[t] = rgb_W0[src * 64 + j];
    }
    if (tid >= 64) {
        const int j = tid - 64;
        const int li = *latent_index;
        const float* lrow = rgb_latent + li * LAT;
        float acc = rgb_b0[j];
        #pragma unroll 8
        for (int l = 0; l < LAT; l++)
            acc = fmaf(lrow[l], rgb_W0[(RGBK + l) * 64 + j], acc);
        sw[LATBo + j] = acc;
    }
    __syncthreads();

    const int p0 = (blockIdx.x * TPB + tid) * 4;

    #pragma unroll
    for (int q = 0; q < 4; q++) {
        u64t Q[4][8];
        {
            const u64t* bp = (const u64t*)(sw + LATBo) + q*8;
            #pragma unroll
            for (int m = 0; m < 8; m++) {
                u64t b = bp[m];
                Q[0][m] = b; Q[1][m] = b; Q[2][m] = b; Q[3][m] = b;
            }
        }
        #pragma unroll 8
        for (int k = 0; k < RGBK; k++) {
            float4 xv = *(const float4*)(g_x + (size_t)k * NPTS + p0);
            u64t xs0, xs1, xs2, xs3;
            PACK_SPLAT(xs0, xv.x); PACK_SPLAT(xs1, xv.y);
            PACK_SPLAT(xs2, xv.z); PACK_SPLAT(xs3, xv.w);
            K4STEP(Q, xs0, xs1, xs2, xs3, sw + k*64 + q*16);
        }
        #pragma unroll
        for (int m = 0; m < 8; m++) {
            unsigned l0,h0,l1,h1,l2,h2,l3,h3;
            UNPACK_F32X2U(l0, h0, Q[0][m]);
            UNPACK_F32X2U(l1, h1, Q[1][m]);
            UNPACK_F32X2U(l2, h2, Q[2][m]);
            UNPACK_F32X2U(l3, h3, Q[3][m]);
            float4 va = make_float4(sp_fast(__uint_as_float(l0)), sp_fast(__uint_as_float(l1)),
                                    sp_fast(__uint_as_float(l2)), sp_fast(__uint_as_float(l3)));
            float4 vb = make_float4(sp_fast(__uint_as_float(h0)), sp_fast(__uint_as_float(h1)),
                                    sp_fast(__uint_as_float(h2)), sp_fast(__uint_as_float(h3)));
            *(float4*)(g_r + (size_t)(q*16 + 2*m)     * NPTS + p0) = va;
            *(float4*)(g_r + (size_t)(q*16 + 2*m + 1) * NPTS + p0) = vb;
        }
    }
}

// ======= k3: rgb L1 (64->64 sp) fused rgb L2 (64->3 sigmoid), 2-pt =========
__global__ __launch_bounds__(TPB, 4)
void k3_rgb12(const float* __restrict__ rgb_W1, const float* __restrict__ rgb_b1,
              const float* __restrict__ rgb_W2, const float* __restrict__ rgb_b2,
              float* __restrict__ out)
{
    __shared__ float sw[64*64 + 64*4 + 64 + 4];
    const int W2o = 64*64, B1o = W2o + 64*4, B2o = B1o + 64;
    const int tid = threadIdx.x;
    for (int t = tid; t < 64*64; t += TPB) sw[t] = rgb_W1[t];
    for (int t = tid; t < 64*3; t += TPB) {
        int k = t / 3, j = t - 3*k;
        sw[W2o + k*4 + j] = rgb_W2[t];
    }
    for (int t = tid; t < 64; t += TPB) sw[W2o + t*4 + 3] = 0.0f;
    if (tid < 64) sw[B1o + tid] = rgb_b1[tid];
    if (tid >= 64 && tid < 67) sw[B2o + tid - 64] = rgb_b2[tid - 64];
    if (tid == 67) sw[B2o + 3] = 0.0f;
    __syncthreads();

    const int p0 = blockIdx.x * (2*TPB) + 2*tid;

    float c00 = sw[B2o+0], c01 = sw[B2o+1], c02 = sw[B2o+2];
    float c10 = c00, c11 = c01, c12 = c02;

    #pragma unroll
    for (int q = 0; q < 4; q++) {
        u64t Q0[8], Q1[8];
        const u64t* bp = (const u64t*)(sw + B1o) + q*8;
        #pragma unroll
        for (int m = 0; m < 8; m++) { Q0[m] = bp[m]; Q1[m] = bp[m]; }

        #pragma unroll 8
        for (int k = 0; k < 64; k++) {
            float2 xv = *(const float2*)(g_r + (size_t)k * NPTS + p0);
            u64t xs0, xs1;
            PACK_SPLAT(xs0, xv.x);
            PACK_SPLAT(xs1, xv.y);
            QSTEP(Q0, Q1, xs0, xs1, sw + k*64 + q*16);
        }

        #pragma unroll
        for (int m = 0; m < 8; m++) {
            unsigned lo, hi;
            UNPACK_F32X2U(lo, hi, Q0[m]);
            float ha = sp_fast(__uint_as_float(lo));
            float hb = sp_fast(__uint_as_float(hi));
            UNPACK_F32X2U(lo, hi, Q1[m]);
            float hc = sp_fast(__uint_as_float(lo));
            float hd = sp_fast(__uint_as_float(hi));
            const int kq = q*16 + 2*m;
            float4 wA = *(const float4*)(sw + W2o + kq*4);
            float4 wB = *(const float4*)(sw + W2o + (kq+1)*4);
            c00 = fmaf(ha, wA.x, c00); c01 = fmaf(ha, wA.y, c01); c02 = fmaf(ha, wA.z, c02);
            c10 = fmaf(hc, wA.x, c10); c11 = fmaf(hc, wA.y, c11); c12 = fmaf(hc, wA.z, c12);
            c00 = fmaf(hb, wB.x, c00); c01 = fmaf(hb, wB.y, c01); c02 = fmaf(hb, wB.z, c02);
            c10 = fmaf(hd, wB.x, c10); c11 = fmaf(hd, wB.y, c11); c12 = fmaf(hd, wB.z, c12);
        }
    }

    const float o0 = out[(size_t)NPTS*4 + p0];
    const float o1 = out[(size_t)NPTS*4 + p0 + 1];
    float4* o4 = (float4*)out;
    o4[p0]     = make_float4(sigmoid_fast(c00), sigmoid_fast(c01), sigmoid_fast(c02), o0);
    o4[p0 + 1] = make_float4(sigmoid_fast(c10), sigmoid_fast(c11), sigmoid_fast(c12), o1);
}

extern "C" void kernel_launch(void* const* d_in, const int* in_sizes, int n_in,
                              void* d_out, int out_size) {
    const float* embedded     = (const float*)d_in[0];
    const float* embedded_dir = (const float*)d_in[1];
    const float* occ_W0 = (const float*)d_in[2];
    const float* occ_b0 = (const float*)d_in[3];
    const float* occ_W1 = (const float*)d_in[4];
    const float* occ_b1 = (const float*)d_in[5];
    const float* occ_W2 = (const float*)d_in[6];
    const float* occ_b2 = (const float*)d_in[7];
    const float* rgb_W0 = (const float*)d_in[8];
    const float* rgb_b0 = (const float*)d_in[9];
    const float* rgb_W1 = (const float*)d_in[10];
    const float* rgb_b1 = (const float*)d_in[11];
    const float* rgb_W2 = (const float*)d_in[12];
    const float* rgb_b2 = (const float*)d_in[13];
    const float* rgb_latent = (const float*)d_in[14];
    const int*   latent_index = (const int*)d_in[15];
    float* out = (float*)d_out;

    const int grid2 = NPTS / (2 * TPB);   // 2048
    const int grid4 = NPTS / (4 * TPB);   // 1024

    k1a_occ0 <<<grid2, TPB>>>(embedded, occ_W0, occ_b0);
    k1b_occ12<<<grid2, TPB>>>(embedded_dir, occ_W1, occ_b1, occ_W2, occ_b2, out);
    k2_rgb0  <<<grid4, TPB>>>(rgb_W0, rgb_b0, rgb_latent, latent_index);
    k3_rgb12 <<<grid2, TPB>>>(rgb_W1, rgb_b1, rgb_W2, rgb_b2, out);
}